// round 11
// baseline (speedup 1.0000x reference)
#include <cuda_runtime.h>
#include <cuda_fp16.h>
#include <cstdint>

// Problem constants
#define NB 4
#define NS 2048
#define NF 512
#define NH 8
#define ND 32
#define HID 256
#define ACTF 16
#define ROWS (NB*NS)          // 8192
#define NP1 768               // x-proj output width (q,k,v only)
#define NC 32                 // chunks per sequence
#define CHUNK 64              // NS / NC
#define EPSF 1e-6f
#define BSCALE 32.0f
#define BUNSCALE 0.03125f

// gemm1 tiling
#define NT1_N 6               // 768/128
#define NT1 (64*NT1_N)        // 384 tiles
#define G1_GRID 296           // 2 CTAs/SM persistent

// ---------------- scratch (static device globals; no allocations) ----------
__device__ __half g_Bt1h[NP1*NF];   // [768,512] W1^T hi (x32)
__device__ __half g_Bt1l[NP1*NF];   // lo
__device__ __half g_Bt2h[NF*HID];   // [512,256] Wout^T hi (x32)
__device__ __half g_Bt2l[NF*HID];
__device__ __half g_xh[ROWS*NF];    // x as fp16 (hi only)
__device__ __half g_o2h[ROWS*HID];  // rms output fp16 (GEMM2 A)
__device__ float g_WbaT[16*NF];     // transposed beta/alpha weights
__device__ float g_ba[ROWS*16];     // beta/alpha raw projections
__device__ float g_proj[ROWS*NP1];
__device__ float g_qn[ROWS*HID];
__device__ float g_kn[ROWS*HID];
__device__ float g_kun[ROWS*HID];
__device__ float g_vu[ROWS*HID];
__device__ float g_sc[ROWS*NH*4];   // beta, Aeff, Bg, ku.k
__device__ float g_u[ROWS*HID];
__device__ float g_w[ROWS*HID];
__device__ float g_cum[32*NC*ND*ND];
__device__ float g_loc[32*NC*ND*ND];
__device__ float g_hinit[32*NC*ND*ND];
__device__ int g_tile_ctr;          // gemm1 persistent tile counter

__device__ __forceinline__ float sigm(float z) { return 1.f / (1.f + __expf(-z)); }

__device__ __forceinline__ uint32_t smem_to_u32(const void* smem_ptr) {
    uint32_t addr;
    asm("{ .reg .u64 tmp; cvta.to.shared.u64 tmp, %1; cvt.u32.u64 %0, tmp; }"
        : "=r"(addr) : "l"(smem_ptr));
    return addr;
}
__device__ __forceinline__ void ldsm_x4(uint32_t* r, uint32_t addr) {
    asm volatile("ldmatrix.sync.aligned.m8n8.x4.shared.b16 {%0,%1,%2,%3}, [%4];"
        : "=r"(r[0]), "=r"(r[1]), "=r"(r[2]), "=r"(r[3]) : "r"(addr));
}
__device__ __forceinline__ void mma16816(float* d, const uint32_t* a, const uint32_t* b) {
    asm volatile(
        "mma.sync.aligned.m16n8k16.row.col.f32.f16.f16.f32 "
        "{%0,%1,%2,%3}, {%4,%5,%6,%7}, {%8,%9}, {%0,%1,%2,%3};"
        : "+f"(d[0]), "+f"(d[1]), "+f"(d[2]), "+f"(d[3])
        : "r"(a[0]), "r"(a[1]), "r"(a[2]), "r"(a[3]), "r"(b[0]), "r"(b[1]));
}
__device__ __forceinline__ void cp16(uint32_t saddr, const void* gaddr) {
    asm volatile("cp.async.cg.shared.global [%0], [%1], 16;" :: "r"(saddr), "l"(gaddr));
}
__device__ __forceinline__ void cp_commit() {
    asm volatile("cp.async.commit_group;" ::: "memory");
}
__device__ __forceinline__ void cp_wait1() {
    asm volatile("cp.async.wait_group 1;" ::: "memory");
}

// ---------------- 1. weight prep (+ tile counter reset) ---------------------
#define N1ELEM (NP1*NF)
#define N2ELEM (NF*HID)
#define N3ELEM (16*NF)
__global__ void prep_weights(const float* __restrict__ Wq, const float* __restrict__ Wk,
                             const float* __restrict__ Wv, const float* __restrict__ Wb,
                             const float* __restrict__ Wa, const float* __restrict__ Wout) {
    int i = blockIdx.x * blockDim.x + threadIdx.x;
    if (i == 0) g_tile_ctr = 0;
    if (i < N1ELEM) {
        int n = i >> 9, k = i & 511;          // Bt1[n,k] = W1[k,n] * 32
        float v;
        if (n < 256)       v = Wq[k*256 + n];
        else if (n < 512)  v = Wk[k*256 + n - 256];
        else               v = Wv[k*256 + n - 512];
        v *= BSCALE;
        __half h = __float2half_rn(v);
        g_Bt1h[i] = h;
        g_Bt1l[i] = __float2half_rn(v - __half2float(h));
    } else if (i < N1ELEM + N2ELEM) {
        int j = i - N1ELEM;
        int n = j >> 8, k = j & 255;          // Bt2[n,k] = Wout[k,n] * 32
        float v = Wout[k*512 + n] * BSCALE;
        __half h = __float2half_rn(v);
        g_Bt2h[j] = h;
        g_Bt2l[j] = __float2half_rn(v - __half2float(h));
    } else if (i < N1ELEM + N2ELEM + N3ELEM) {
        int j = i - N1ELEM - N2ELEM;
        int jj = j >> 9, k = j & 511;         // WbaT[jj][k]
        g_WbaT[j] = (jj < 8) ? Wb[k*8 + jj] : Wa[k*8 + (jj - 8)];
    }
}

// ------- 1b. fused: x -> fp16 + beta/alpha projections (one pass over x) ----
__global__ __launch_bounds__(256) void xprep_kernel(const float* __restrict__ x) {
    int w = blockIdx.x * 8 + (threadIdx.x >> 5);     // bs row
    int lane = threadIdx.x & 31;
    const float4* xr = (const float4*)(x + (size_t)w * NF);   // 128 float4/row

    float4 xv[4];
#pragma unroll
    for (int i = 0; i < 4; i++) xv[i] = xr[lane + i * 32];

    // emit fp16 copy (coalesced)
#pragma unroll
    for (int i = 0; i < 4; i++) {
        __half2 p0 = __floats2half2_rn(xv[i].x, xv[i].y);
        __half2 p1 = __floats2half2_rn(xv[i].z, xv[i].w);
        uint2 hp;
        hp.x = *(uint32_t*)&p0;
        hp.y = *(uint32_t*)&p1;
        *(uint2*)(g_xh + (size_t)w * NF + (lane + i * 32) * 4) = hp;
    }

    // beta/alpha: 16 exact fp32 dot-products over the row
#pragma unroll
    for (int j = 0; j < 16; j++) {
        const float4* wt = (const float4*)(g_WbaT + j * NF);
        float s = 0.f;
#pragma unroll
        for (int i = 0; i < 4; i++) {
            float4 wv = wt[lane + i * 32];
            s += xv[i].x*wv.x + xv[i].y*wv.y + xv[i].z*wv.z + xv[i].w*wv.w;
        }
#pragma unroll
        for (int o = 16; o > 0; o >>= 1) s += __shfl_xor_sync(0xffffffffu, s, o);
        if (lane == 0) g_ba[w * 16 + j] = s;
    }
}

// ---------------- 2. HMMA split-fp16 GEMM, 3-stage cp.async ------------------
// C = Ah(fp16) @ (Bh+Bl)(fp16,x32)^T * (1/32) (+bias). Tile 128x128, BK=32.
#define ROWB 80                 // padded smem row stride (bytes)
#define OAH 0
#define OBH 10240
#define OBL 20480
#define STG 30720
#define STAGES 3
#define SMEM_TOTAL (STAGES*STG)

// Computes one 128x128 tile. Caller provides m0,n0 and smem base.
__device__ __forceinline__ void gemm_tile(const __half* __restrict__ Ah,
                                          const __half* __restrict__ Bh,
                                          const __half* __restrict__ Bl,
                                          float* __restrict__ C,
                                          const float* __restrict__ bias,
                                          int N, int K, int m0, int n0,
                                          char* smem, uint32_t sb) {
    int tid = threadIdx.x, lane = tid & 31, wid = tid >> 5;
    int wm = (wid >> 2) * 64, wn = (wid & 3) * 32;

    uint32_t aOff = (uint32_t)((wm + (lane & 7) + ((lane >> 3) & 1) * 8) * ROWB
                               + ((lane >> 4) * 8) * 2);
    uint32_t bOff = (uint32_t)((wn + (lane & 7) + ((lane >> 4) & 1) * 8) * ROWB
                               + (((lane >> 3) & 1) * 8) * 2);

    float acc[4][4][4];
#pragma unroll
    for (int mt = 0; mt < 4; mt++)
#pragma unroll
        for (int nt = 0; nt < 4; nt++)
#pragma unroll
            for (int e = 0; e < 4; e++) acc[mt][nt][e] = 0.f;

    int crow = tid >> 1;
    int cel = (tid & 1) * 16;
    uint32_t sOff = (uint32_t)(crow * ROWB + (tid & 1) * 32);
    const __half* pAh = Ah + (size_t)(m0 + crow) * K + cel;
    const __half* pBh = Bh + (size_t)(n0 + crow) * K + cel;
    const __half* pBl = Bl + (size_t)(n0 + crow) * K + cel;
    int nkc = K >> 5;

#define CP_STAGE(kc, s) do {                                            \
        uint32_t _stb = sb + (s) * STG;                                 \
        int _ko = (kc) * 32;                                            \
        cp16(_stb + OAH + sOff,      pAh + _ko);                        \
        cp16(_stb + OAH + sOff + 16, pAh + _ko + 8);                    \
        cp16(_stb + OBH + sOff,      pBh + _ko);                        \
        cp16(_stb + OBH + sOff + 16, pBh + _ko + 8);                    \
        cp16(_stb + OBL + sOff,      pBl + _ko);                        \
        cp16(_stb + OBL + sOff + 16, pBl + _ko + 8);                    \
    } while(0)

    CP_STAGE(0, 0); cp_commit();
    CP_STAGE(1, 1); cp_commit();

    int s = 0;
    for (int kc = 0; kc < nkc; kc++) {
        cp_wait1();
        __syncthreads();

        int kn = kc + 2;
        if (kn < nkc) CP_STAGE(kn, (s + 2 >= STAGES) ? s + 2 - STAGES : s + 2);
        cp_commit();

        uint32_t stb = sb + s * STG;
#pragma unroll
        for (int ks = 0; ks < 2; ks++) {
            uint32_t kb = ks * 32;
            uint32_t af[4][4], bhF[2][4], blF[2][4];
#pragma unroll
            for (int mt = 0; mt < 4; mt++)
                ldsm_x4(af[mt], stb + OAH + aOff + mt * (16 * ROWB) + kb);
#pragma unroll
            for (int np = 0; np < 2; np++) {
                ldsm_x4(bhF[np], stb + OBH + bOff + np * (16 * ROWB) + kb);
                ldsm_x4(blF[np], stb + OBL + bOff + np * (16 * ROWB) + kb);
            }
#pragma unroll
            for (int mt = 0; mt < 4; mt++)
#pragma unroll
                for (int nt = 0; nt < 4; nt++)
                    mma16816(acc[mt][nt], af[mt], &bhF[nt >> 1][(nt & 1) * 2]);
#pragma unroll
            for (int mt = 0; mt < 4; mt++)
#pragma unroll
                for (int nt = 0; nt < 4; nt++)
                    mma16816(acc[mt][nt], af[mt], &blF[nt >> 1][(nt & 1) * 2]);
        }
        s = (s + 1 >= STAGES) ? 0 : s + 1;
    }
#undef CP_STAGE

#pragma unroll
    for (int mt = 0; mt < 4; mt++) {
        int r0 = m0 + wm + mt * 16 + (lane >> 2);
#pragma unroll
        for (int nt = 0; nt < 4; nt++) {
            int col = n0 + wn + nt * 8 + (lane & 3) * 2;
            float b0 = 0.f, b1 = 0.f;
            if (bias) { b0 = bias[col]; b1 = bias[col + 1]; }
            float2 v0, v1;
            v0.x = acc[mt][nt][0] * BUNSCALE + b0; v0.y = acc[mt][nt][1] * BUNSCALE + b1;
            v1.x = acc[mt][nt][2] * BUNSCALE + b0; v1.y = acc[mt][nt][3] * BUNSCALE + b1;
            *(float2*)(C + (size_t)r0 * N + col) = v0;
            *(float2*)(C + (size_t)(r0 + 8) * N + col) = v1;
        }
    }
}

// gemm1: persistent CTAs, dynamic tile scheduler
__global__ __launch_bounds__(256, 2) void gemm1_tc() {
    extern __shared__ char smem[];
    __shared__ int s_tile;
    uint32_t sb = smem_to_u32(smem);
    for (;;) {
        if (threadIdx.x == 0) s_tile = atomicAdd(&g_tile_ctr, 1);
        __syncthreads();                 // also guards smem reuse across tiles
        int tile = s_tile;
        if (tile >= NT1) return;
        int m0 = (tile / NT1_N) * 128;
        int n0 = (tile % NT1_N) * 128;
        gemm_tile(g_xh, g_Bt1h, g_Bt1l, g_proj, nullptr, NP1, NF, m0, n0, smem, sb);
    }
}
// gemm2: static grid (256 CTAs = single wave)
__global__ __launch_bounds__(256, 2) void gemm2_tc(const float* __restrict__ bout,
                                                   float* __restrict__ y) {
    extern __shared__ char smem[];
    uint32_t sb = smem_to_u32(smem);
    gemm_tile(g_o2h, g_Bt2h, g_Bt2l, y, bout, NF, HID,
              blockIdx.y * 128, blockIdx.x * 128, smem, sb);
}

// ------- 3. activations + l2norm + fused action proj (coalesced weights) ----
__global__ __launch_bounds__(256) void act_kernel(const float* __restrict__ mask,
                                                  const float* __restrict__ action,
                                                  const float* __restrict__ Wku,
                                                  const float* __restrict__ Wvu,
                                                  const float* __restrict__ Wg) {
    int w = (blockIdx.x * blockDim.x + threadIdx.x) >> 5;   // (b*S+s)*H + h
    int lane = threadIdx.x & 31;
    if (w >= ROWS * NH) return;
    int bs = w >> 3, h = w & 7;
    int pb = bs * NP1;

    const float4* ar4 = (const float4*)(action + bs * ACTF);
    float4 a0 = ar4[0], a1 = ar4[1], a2 = ar4[2], a3 = ar4[3];
    float a[ACTF] = { a0.x,a0.y,a0.z,a0.w, a1.x,a1.y,a1.z,a1.w,
                      a2.x,a2.y,a2.z,a2.w, a3.x,a3.y,a3.z,a3.w };

    int c = h * 32 + lane;
    float kur = 0.f, vur = 0.f, gr = 0.f;
#pragma unroll
    for (int k2 = 0; k2 < ACTF; k2++) {
        kur += a[k2] * Wku[k2 * HID + c];
        vur += a[k2] * Wvu[k2 * HID + c];
        gr  += a[k2] * Wg[k2 * NH + h];
    }

    float qr  = g_proj[pb + h*32 + lane];
    float kr  = g_proj[pb + 256 + h*32 + lane];

    float q  = qr * sigm(qr);
    float k  = kr * sigm(kr);
    float ku = kur * sigm(kur);

    float sq = q*q, sk = k*k, sku = ku*ku;
#pragma unroll
    for (int o = 16; o > 0; o >>= 1) {
        sq  += __shfl_xor_sync(0xffffffffu, sq,  o);
        sk  += __shfl_xor_sync(0xffffffffu, sk,  o);
        sku += __shfl_xor_sync(0xffffffffu, sku, o);
    }
    q  *= rsqrtf(sq  + EPSF);
    k  *= rsqrtf(sk  + EPSF);
    ku *= rsqrtf(sku + EPSF);

    float dk = ku * k;
#pragma unroll
    for (int o = 16; o > 0; o >>= 1) dk += __shfl_xor_sync(0xffffffffu, dk, o);

    int base = w * 32;
    g_qn[base + lane]  = q;
    g_kn[base + lane]  = k;
    g_kun[base + lane] = ku;
    g_vu[base + lane]  = vur;
    if (lane == 0) {
        float br = g_ba[bs * 16 + h];
        float ar = g_ba[bs * 16 + 8 + h];
        float m  = mask[bs];
        g_sc[w*4 + 0] = sigm(br);                 // beta
        g_sc[w*4 + 1] = sigm(ar) * (1.f - m);     // Aeff
        g_sc[w*4 + 2] = sigm(gr);                 // Bg
        g_sc[w*4 + 3] = dk;                       // ku . k
    }
}

// ---------------- 5. phase 1: chunked scan, smem-broadcast operands ---------
__global__ __launch_bounds__(128) void phase1() {
    __shared__ float sk[4][32], sq[4][32], sku[4][32];
    int wq = threadIdx.x >> 5;
    int wg = blockIdx.x * 4 + wq;                   // 0..1023
    int lane = threadIdx.x & 31;
    int chain = wg >> 5;        // b*8+h
    int c = wg & 31;
    int b = chain >> 3, h = chain & 7;

    float cum[32], hl[32];
#pragma unroll
    for (int j = 0; j < 32; j++) { cum[j] = (j == lane) ? 1.f : 0.f; hl[j] = 0.f; }

    int t0 = c * CHUNK;
    int bs0 = b * NS + t0;
    int base = (bs0 * NH + h) * 32;
    float kreg  = g_kn[base + lane];
    float qreg  = g_qn[base + lane];
    float kureg = g_kun[base + lane];
    float vs    = g_proj[bs0 * NP1 + 512 + h * 32 + lane];
    float vu    = g_vu[base + lane];
    float4 scv  = *(const float4*)&g_sc[(bs0 * NH + h) * 4];

    for (int t = t0; t < t0 + CHUNK; t++) {
        __syncwarp();
        sk[wq][lane]  = kreg;
        sq[wq][lane]  = qreg;
        sku[wq][lane] = kureg;
        __syncwarp();

        float kN = 0.f, qN = 0.f, kuN = 0.f, vsN = 0.f, vuN = 0.f;
        float4 scN = scv;
        int base2 = base;
        if (t + 1 < t0 + CHUNK) {
            int bs2 = b * NS + t + 1;
            int w2 = bs2 * NH + h;
            base2 = w2 * 32;
            kN  = g_kn[base2 + lane];
            qN  = g_qn[base2 + lane];
            kuN = g_kun[base2 + lane];
            vsN = g_proj[bs2 * NP1 + 512 + h * 32 + lane];
            vuN = g_vu[base2 + lane];
            scN = *(const float4*)&g_sc[w2 * 4];
        }

        float beta = scv.x, Ae = scv.y, Bg = scv.z, kuk = scv.w;
        float ck = 0.f, hk = 0.f;
#pragma unroll
        for (int j4 = 0; j4 < 8; j4++) {
            float4 k4 = *(const float4*)&sk[wq][j4 * 4];
            ck += cum[j4*4+0]*k4.x + cum[j4*4+1]*k4.y + cum[j4*4+2]*k4.z + cum[j4*4+3]*k4.w;
            hk += hl[j4*4+0]*k4.x  + hl[j4*4+1]*k4.y  + hl[j4*4+2]*k4.z  + hl[j4*4+3]*k4.w;
        }
        float e  = Ae * beta * ck;
        float cc = beta * vs - Ae * beta * hk - Bg * beta * kuk * vu;
        float dd = Bg * vu;

        float u = 0.f, wv = 0.f;
#pragma unroll
        for (int j4 = 0; j4 < 8; j4++) {
            float4 k4  = *(const float4*)&sk[wq][j4 * 4];
            float4 ku4 = *(const float4*)&sku[wq][j4 * 4];
            float4 q4  = *(const float4*)&sq[wq][j4 * 4];
            int j = j4 * 4;
            cum[j+0] = Ae * cum[j+0] - e * k4.x;
            cum[j+1] = Ae * cum[j+1] - e * k4.y;
            cum[j+2] = Ae * cum[j+2] - e * k4.z;
            cum[j+3] = Ae * cum[j+3] - e * k4.w;
            hl[j+0] = Ae * hl[j+0] + cc * k4.x + dd * ku4.x;
            hl[j+1] = Ae * hl[j+1] + cc * k4.y + dd * ku4.y;
            hl[j+2] = Ae * hl[j+2] + cc * k4.z + dd * ku4.z;
            hl[j+3] = Ae * hl[j+3] + cc * k4.w + dd * ku4.w;
            u  += cum[j+0]*q4.x + cum[j+1]*q4.y + cum[j+2]*q4.z + cum[j+3]*q4.w;
            wv += hl[j+0]*q4.x  + hl[j+1]*q4.y  + hl[j+2]*q4.z  + hl[j+3]*q4.w;
        }
        g_u[base + lane] = u;
        g_w[base + lane] = wv;

        kreg = kN; qreg = qN; kureg = kuN; vs = vsN; vu = vuN; scv = scN;
        base = base2;
    }
    int mb = (chain * NC + c) * 1024 + lane * 32;
#pragma unroll
    for (int j = 0; j < 32; j += 4) {
        *(float4*)&g_cum[mb + j] = make_float4(cum[j], cum[j+1], cum[j+2], cum[j+3]);
        *(float4*)&g_loc[mb + j] = make_float4(hl[j],  hl[j+1],  hl[j+2],  hl[j+3]);
    }
}

// ---------------- 6. phase 2: fold chunks (smem-staged, prefetched) ---------
__global__ __launch_bounds__(1024) void phase2(const float* __restrict__ carry,
                                               float* __restrict__ outCarry) {
    __shared__ float cumS[2][1024];
    int chain = blockIdx.x;
    int tid = threadIdx.x;
    int j = tid & 31;
    float hreg = carry[chain * 1024 + tid];

    int mb0 = (chain * NC) * 1024;
    float cumNext = g_cum[mb0 + tid];
    float locNext = g_loc[mb0 + tid];

    for (int c = 0; c < NC; c++) {
        int s = c & 1;
        cumS[s][tid] = cumNext;
        float locCur = locNext;
        __syncthreads();
        if (c + 1 < NC) {
            int mb1 = (chain * NC + c + 1) * 1024;
            cumNext = g_cum[mb1 + tid];
            locNext = g_loc[mb1 + tid];
        }
        g_hinit[(chain * NC + c) * 1024 + tid] = hreg;
        float nv = locCur;
#pragma unroll
        for (int m = 0; m < 32; m++)
            nv += __shfl_sync(0xffffffffu, hreg, m) * cumS[s][m * 32 + j];
        hreg = nv;
    }
    outCarry[chain * 1024 + tid] = hreg;  // new_carry
}

// --------- 7. fused phase3 + rms -> fp16: block per (b, chunk) ---------------
__global__ __launch_bounds__(512) void phase3_rms(const float* __restrict__ scale) {
    __shared__ float hin[NH][32 * 33];
    __shared__ float sscale[HID];
    __shared__ float partial[2][2][NH];
    int blk = blockIdx.x;            // b*NC + c
    int b = blk >> 5, c = blk & 31;
    int tid = threadIdx.x;
    int wid = tid >> 5, lane = tid & 31;
    int h = wid & 7, half = wid >> 3;

    for (int idx = tid; idx < NH * 1024; idx += 512) {
        int hh = idx >> 10, e = idx & 1023;
        int i = e >> 5, jj = e & 31;
        hin[hh][i * 33 + jj] = g_hinit[(((b * NH + hh) * NC) + c) * 1024 + e];
    }
    if (tid < HID) sscale[tid] = scale[tid];
    __syncthreads();

    for (int it = 0; it < 32; it++) {
        int t = c * CHUNK + half * 32 + it;
        int bsrow = b * NS + t;
        int base = (bsrow * NH + h) * 32;
        float ul  = g_u[base + lane];
        float acc = g_w[base + lane];
#pragma unroll
        for (int j = 0; j < 32; j++)
            acc += hin[h][lane * 33 + j] * __shfl_sync(0xffffffffu, ul, j);

        float ss = acc * acc;
#pragma unroll
        for (int o = 16; o > 0; o >>= 1) ss += __shfl_xor_sync(0xffffffffu, ss, o);
        int sBuf = it & 1;
        if (lane == 0) partial[half][sBuf][h] = ss;
        __syncthreads();
        float tot = partial[half][sBuf][0] + partial[half][sBuf][1]
                  + partial[half][sBuf][2] + partial[half][sBuf][3]
                  + partial[half][sBuf][4] + partial[half][sBuf][5]
                  + partial[half][sBuf][6] + partial[half][sBuf][7];
        float inv = rsqrtf(tot * (1.f / 256.f) + EPSF);
        float o = acc * inv * sscale[h * 32 + lane];
        g_o2h[bsrow * HID + h * 32 + lane] = __float2half_rn(o);
    }
}

// ---------------- launcher ---------------------------------------------------
extern "C" void kernel_launch(void* const* d_in, const int* in_sizes, int n_in,
                              void* d_out, int out_size) {
    const float* x      = (const float*)d_in[0];
    const float* action = (const float*)d_in[1];
    const float* mask   = (const float*)d_in[2];
    const float* carry  = (const float*)d_in[3];
    const float* Wq     = (const float*)d_in[4];
    const float* Wk     = (const float*)d_in[5];
    const float* Wv     = (const float*)d_in[6];
    const float* Wbeta  = (const float*)d_in[7];
    const float* Walpha = (const float*)d_in[8];
    const float* Wku    = (const float*)d_in[9];
    const float* Wvu    = (const float*)d_in[10];
    const float* Wgamma = (const float*)d_in[11];
    const float* rmssc  = (const float*)d_in[12];
    const float* Wout   = (const float*)d_in[13];
    const float* bout   = (const float*)d_in[14];

    float* outCarry = (float*)d_out;                       // (B,H,D,D) = 32768
    float* y        = (float*)d_out + NB * NH * ND * ND;   // (B,S,F)

    cudaFuncSetAttribute(gemm1_tc, cudaFuncAttributeMaxDynamicSharedMemorySize, SMEM_TOTAL);
    cudaFuncSetAttribute(gemm2_tc, cudaFuncAttributeMaxDynamicSharedMemorySize, SMEM_TOTAL);

    int nprep = N1ELEM + N2ELEM + N3ELEM;
    prep_weights<<<(nprep + 255) / 256, 256>>>(Wq, Wk, Wv, Wbeta, Walpha, Wout);
    xprep_kernel<<<ROWS / 8, 256>>>(x);

    gemm1_tc<<<G1_GRID, 256, SMEM_TOTAL>>>();

    act_kernel<<<(ROWS * NH * 32) / 256, 256>>>(mask, action, Wku, Wvu, Wgamma);

    phase1<<<256, 128>>>();
    phase2<<<32, 1024>>>(carry, outCarry);
    phase3_rms<<<NB * NC, 512>>>(rmssc);

    dim3 g2(NF / 128, ROWS / 128);        // (4, 64)
    gemm2_tc<<<g2, 256, SMEM_TOTAL>>>(bout, y);
}

// round 12
// speedup vs baseline: 1.0795x; 1.0795x over previous
#include <cuda_runtime.h>
#include <cuda_fp16.h>
#include <cstdint>

// Problem constants
#define NB 4
#define NS 2048
#define NF 512
#define NH 8
#define ND 32
#define HID 256
#define ACTF 16
#define ROWS (NB*NS)          // 8192
#define NP1 768               // x-proj output width (q,k,v only)
#define NC 32                 // chunks per sequence
#define CHUNK 64              // NS / NC
#define EPSF 1e-6f

// gemm1 tiling
#define NT1_N 6               // 768/128
#define NT1 (64*NT1_N)        // 384 tiles
#define G1_GRID 296           // 2 CTAs/SM persistent

// ---------------- scratch (static device globals; no allocations) ----------
__device__ __half g_Bt1h[NP1*NF];   // [768,512] W1^T fp16
__device__ __half g_Bt2h[NF*HID];   // [512,256] Wout^T fp16
__device__ __half g_xh[ROWS*NF];    // x as fp16
__device__ __half g_o2h[ROWS*HID];  // rms output fp16 (GEMM2 A)
__device__ float g_WbaT[16*NF];     // transposed beta/alpha weights
__device__ float g_ba[ROWS*16];     // beta/alpha raw projections
__device__ float g_proj[ROWS*NP1];
__device__ float g_qn[ROWS*HID];
__device__ float g_kn[ROWS*HID];
__device__ float g_kun[ROWS*HID];
__device__ float g_vu[ROWS*HID];
__device__ float g_sc[ROWS*NH*4];   // beta, Aeff, Bg, ku.k
__device__ float g_u[ROWS*HID];
__device__ float g_w[ROWS*HID];
__device__ float g_cum[32*NC*ND*ND];
__device__ float g_loc[32*NC*ND*ND];
__device__ float g_hinit[32*NC*ND*ND];
__device__ int g_tile_ctr;          // gemm1 persistent tile counter

__device__ __forceinline__ float sigm(float z) { return 1.f / (1.f + __expf(-z)); }

__device__ __forceinline__ uint32_t smem_to_u32(const void* smem_ptr) {
    uint32_t addr;
    asm("{ .reg .u64 tmp; cvta.to.shared.u64 tmp, %1; cvt.u32.u64 %0, tmp; }"
        : "=r"(addr) : "l"(smem_ptr));
    return addr;
}
__device__ __forceinline__ void ldsm_x4(uint32_t* r, uint32_t addr) {
    asm volatile("ldmatrix.sync.aligned.m8n8.x4.shared.b16 {%0,%1,%2,%3}, [%4];"
        : "=r"(r[0]), "=r"(r[1]), "=r"(r[2]), "=r"(r[3]) : "r"(addr));
}
__device__ __forceinline__ void mma16816(float* d, const uint32_t* a, const uint32_t* b) {
    asm volatile(
        "mma.sync.aligned.m16n8k16.row.col.f32.f16.f16.f32 "
        "{%0,%1,%2,%3}, {%4,%5,%6,%7}, {%8,%9}, {%0,%1,%2,%3};"
        : "+f"(d[0]), "+f"(d[1]), "+f"(d[2]), "+f"(d[3])
        : "r"(a[0]), "r"(a[1]), "r"(a[2]), "r"(a[3]), "r"(b[0]), "r"(b[1]));
}
__device__ __forceinline__ void cp16(uint32_t saddr, const void* gaddr) {
    asm volatile("cp.async.cg.shared.global [%0], [%1], 16;" :: "r"(saddr), "l"(gaddr));
}
__device__ __forceinline__ void cp_commit() {
    asm volatile("cp.async.commit_group;" ::: "memory");
}
__device__ __forceinline__ void cp_wait1() {
    asm volatile("cp.async.wait_group 1;" ::: "memory");
}

// ---------------- 1. weight prep (+ tile counter reset) ---------------------
#define N1ELEM (NP1*NF)
#define N2ELEM (NF*HID)
#define N3ELEM (16*NF)
__global__ void prep_weights(const float* __restrict__ Wq, const float* __restrict__ Wk,
                             const float* __restrict__ Wv, const float* __restrict__ Wb,
                             const float* __restrict__ Wa, const float* __restrict__ Wout) {
    int i = blockIdx.x * blockDim.x + threadIdx.x;
    if (i == 0) g_tile_ctr = 0;
    if (i < N1ELEM) {
        int n = i >> 9, k = i & 511;          // Bt1[n,k] = W1[k,n]
        float v;
        if (n < 256)       v = Wq[k*256 + n];
        else if (n < 512)  v = Wk[k*256 + n - 256];
        else               v = Wv[k*256 + n - 512];
        g_Bt1h[i] = __float2half_rn(v);
    } else if (i < N1ELEM + N2ELEM) {
        int j = i - N1ELEM;
        int n = j >> 8, k = j & 255;          // Bt2[n,k] = Wout[k,n]
        g_Bt2h[j] = __float2half_rn(Wout[k*512 + n]);
    } else if (i < N1ELEM + N2ELEM + N3ELEM) {
        int j = i - N1ELEM - N2ELEM;
        int jj = j >> 9, k = j & 511;         // WbaT[jj][k]
        g_WbaT[j] = (jj < 8) ? Wb[k*8 + jj] : Wa[k*8 + (jj - 8)];
    }
}

// ------- 1b. fused: x -> fp16 + beta/alpha projections (one pass over x) ----
__global__ __launch_bounds__(256) void xprep_kernel(const float* __restrict__ x) {
    int w = blockIdx.x * 8 + (threadIdx.x >> 5);     // bs row
    int lane = threadIdx.x & 31;
    const float4* xr = (const float4*)(x + (size_t)w * NF);   // 128 float4/row

    float4 xv[4];
#pragma unroll
    for (int i = 0; i < 4; i++) xv[i] = xr[lane + i * 32];

    // emit fp16 copy (coalesced)
#pragma unroll
    for (int i = 0; i < 4; i++) {
        __half2 p0 = __floats2half2_rn(xv[i].x, xv[i].y);
        __half2 p1 = __floats2half2_rn(xv[i].z, xv[i].w);
        uint2 hp;
        hp.x = *(uint32_t*)&p0;
        hp.y = *(uint32_t*)&p1;
        *(uint2*)(g_xh + (size_t)w * NF + (lane + i * 32) * 4) = hp;
    }

    // beta/alpha: 16 exact fp32 dot-products over the row
#pragma unroll
    for (int j = 0; j < 16; j++) {
        const float4* wt = (const float4*)(g_WbaT + j * NF);
        float s = 0.f;
#pragma unroll
        for (int i = 0; i < 4; i++) {
            float4 wv = wt[lane + i * 32];
            s += xv[i].x*wv.x + xv[i].y*wv.y + xv[i].z*wv.z + xv[i].w*wv.w;
        }
#pragma unroll
        for (int o = 16; o > 0; o >>= 1) s += __shfl_xor_sync(0xffffffffu, s, o);
        if (lane == 0) g_ba[w * 16 + j] = s;
    }
}

// ---------------- 2. HMMA fp16 GEMM (single product), 3-stage cp.async ------
// C = A(fp16) @ B(fp16)^T (+bias). Tile 128x128, BK=32.
#define ROWB 80                 // padded smem row stride (bytes)
#define OAH 0
#define OBH 10240
#define STG 20480
#define STAGES 3
#define SMEM_TOTAL (STAGES*STG)

__device__ __forceinline__ void gemm_tile(const __half* __restrict__ Ah,
                                          const __half* __restrict__ Bh,
                                          float* __restrict__ C,
                                          const float* __restrict__ bias,
                                          int N, int K, int m0, int n0,
                                          char* smem, uint32_t sb) {
    int tid = threadIdx.x, lane = tid & 31, wid = tid >> 5;
    int wm = (wid >> 2) * 64, wn = (wid & 3) * 32;

    uint32_t aOff = (uint32_t)((wm + (lane & 7) + ((lane >> 3) & 1) * 8) * ROWB
                               + ((lane >> 4) * 8) * 2);
    uint32_t bOff = (uint32_t)((wn + (lane & 7) + ((lane >> 4) & 1) * 8) * ROWB
                               + (((lane >> 3) & 1) * 8) * 2);

    float acc[4][4][4];
#pragma unroll
    for (int mt = 0; mt < 4; mt++)
#pragma unroll
        for (int nt = 0; nt < 4; nt++)
#pragma unroll
            for (int e = 0; e < 4; e++) acc[mt][nt][e] = 0.f;

    int crow = tid >> 1;
    int cel = (tid & 1) * 16;
    uint32_t sOff = (uint32_t)(crow * ROWB + (tid & 1) * 32);
    const __half* pAh = Ah + (size_t)(m0 + crow) * K + cel;
    const __half* pBh = Bh + (size_t)(n0 + crow) * K + cel;
    int nkc = K >> 5;

#define CP_STAGE(kc, s) do {                                            \
        uint32_t _stb = sb + (s) * STG;                                 \
        int _ko = (kc) * 32;                                            \
        cp16(_stb + OAH + sOff,      pAh + _ko);                        \
        cp16(_stb + OAH + sOff + 16, pAh + _ko + 8);                    \
        cp16(_stb + OBH + sOff,      pBh + _ko);                        \
        cp16(_stb + OBH + sOff + 16, pBh + _ko + 8);                    \
    } while(0)

    CP_STAGE(0, 0); cp_commit();
    CP_STAGE(1, 1); cp_commit();

    int s = 0;
    for (int kc = 0; kc < nkc; kc++) {
        cp_wait1();
        __syncthreads();

        int kn = kc + 2;
        if (kn < nkc) CP_STAGE(kn, (s + 2 >= STAGES) ? s + 2 - STAGES : s + 2);
        cp_commit();

        uint32_t stb = sb + s * STG;
#pragma unroll
        for (int ks = 0; ks < 2; ks++) {
            uint32_t kb = ks * 32;
            uint32_t af[4][4], bhF[2][4];
#pragma unroll
            for (int mt = 0; mt < 4; mt++)
                ldsm_x4(af[mt], stb + OAH + aOff + mt * (16 * ROWB) + kb);
#pragma unroll
            for (int np = 0; np < 2; np++)
                ldsm_x4(bhF[np], stb + OBH + bOff + np * (16 * ROWB) + kb);
#pragma unroll
            for (int mt = 0; mt < 4; mt++)
#pragma unroll
                for (int nt = 0; nt < 4; nt++)
                    mma16816(acc[mt][nt], af[mt], &bhF[nt >> 1][(nt & 1) * 2]);
        }
        s = (s + 1 >= STAGES) ? 0 : s + 1;
    }
#undef CP_STAGE

#pragma unroll
    for (int mt = 0; mt < 4; mt++) {
        int r0 = m0 + wm + mt * 16 + (lane >> 2);
#pragma unroll
        for (int nt = 0; nt < 4; nt++) {
            int col = n0 + wn + nt * 8 + (lane & 3) * 2;
            float b0 = 0.f, b1 = 0.f;
            if (bias) { b0 = bias[col]; b1 = bias[col + 1]; }
            float2 v0, v1;
            v0.x = acc[mt][nt][0] + b0; v0.y = acc[mt][nt][1] + b1;
            v1.x = acc[mt][nt][2] + b0; v1.y = acc[mt][nt][3] + b1;
            *(float2*)(C + (size_t)r0 * N + col) = v0;
            *(float2*)(C + (size_t)(r0 + 8) * N + col) = v1;
        }
    }
}

// gemm1: persistent CTAs, dynamic tile scheduler
__global__ __launch_bounds__(256, 2) void gemm1_tc() {
    extern __shared__ char smem[];
    __shared__ int s_tile;
    uint32_t sb = smem_to_u32(smem);
    for (;;) {
        if (threadIdx.x == 0) s_tile = atomicAdd(&g_tile_ctr, 1);
        __syncthreads();
        int tile = s_tile;
        if (tile >= NT1) return;
        int m0 = (tile / NT1_N) * 128;
        int n0 = (tile % NT1_N) * 128;
        gemm_tile(g_xh, g_Bt1h, g_proj, nullptr, NP1, NF, m0, n0, smem, sb);
    }
}
// gemm2: static grid (256 CTAs = single wave)
__global__ __launch_bounds__(256, 2) void gemm2_tc(const float* __restrict__ bout,
                                                   float* __restrict__ y) {
    extern __shared__ char smem[];
    uint32_t sb = smem_to_u32(smem);
    gemm_tile(g_o2h, g_Bt2h, y, bout, NF, HID,
              blockIdx.y * 128, blockIdx.x * 128, smem, sb);
}

// ------- 3. activations + l2norm + fused action proj (coalesced weights) ----
__global__ __launch_bounds__(256) void act_kernel(const float* __restrict__ mask,
                                                  const float* __restrict__ action,
                                                  const float* __restrict__ Wku,
                                                  const float* __restrict__ Wvu,
                                                  const float* __restrict__ Wg) {
    int w = (blockIdx.x * blockDim.x + threadIdx.x) >> 5;   // (b*S+s)*H + h
    int lane = threadIdx.x & 31;
    if (w >= ROWS * NH) return;
    int bs = w >> 3, h = w & 7;
    int pb = bs * NP1;

    const float4* ar4 = (const float4*)(action + bs * ACTF);
    float4 a0 = ar4[0], a1 = ar4[1], a2 = ar4[2], a3 = ar4[3];
    float a[ACTF] = { a0.x,a0.y,a0.z,a0.w, a1.x,a1.y,a1.z,a1.w,
                      a2.x,a2.y,a2.z,a2.w, a3.x,a3.y,a3.z,a3.w };

    int c = h * 32 + lane;
    float kur = 0.f, vur = 0.f, gr = 0.f;
#pragma unroll
    for (int k2 = 0; k2 < ACTF; k2++) {
        kur += a[k2] * Wku[k2 * HID + c];
        vur += a[k2] * Wvu[k2 * HID + c];
        gr  += a[k2] * Wg[k2 * NH + h];
    }

    float qr  = g_proj[pb + h*32 + lane];
    float kr  = g_proj[pb + 256 + h*32 + lane];

    float q  = qr * sigm(qr);
    float k  = kr * sigm(kr);
    float ku = kur * sigm(kur);

    float sq = q*q, sk = k*k, sku = ku*ku;
#pragma unroll
    for (int o = 16; o > 0; o >>= 1) {
        sq  += __shfl_xor_sync(0xffffffffu, sq,  o);
        sk  += __shfl_xor_sync(0xffffffffu, sk,  o);
        sku += __shfl_xor_sync(0xffffffffu, sku, o);
    }
    q  *= rsqrtf(sq  + EPSF);
    k  *= rsqrtf(sk  + EPSF);
    ku *= rsqrtf(sku + EPSF);

    float dk = ku * k;
#pragma unroll
    for (int o = 16; o > 0; o >>= 1) dk += __shfl_xor_sync(0xffffffffu, dk, o);

    int base = w * 32;
    g_qn[base + lane]  = q;
    g_kn[base + lane]  = k;
    g_kun[base + lane] = ku;
    g_vu[base + lane]  = vur;
    if (lane == 0) {
        float br = g_ba[bs * 16 + h];
        float ar = g_ba[bs * 16 + 8 + h];
        float m  = mask[bs];
        g_sc[w*4 + 0] = sigm(br);                 // beta
        g_sc[w*4 + 1] = sigm(ar) * (1.f - m);     // Aeff
        g_sc[w*4 + 2] = sigm(gr);                 // Bg
        g_sc[w*4 + 3] = dk;                       // ku . k
    }
}

// ---------------- 5. phase 1: chunked scan, smem-broadcast operands ---------
__global__ __launch_bounds__(128) void phase1() {
    __shared__ float sk[4][32], sq[4][32], sku[4][32];
    int wq = threadIdx.x >> 5;
    int wg = blockIdx.x * 4 + wq;                   // 0..1023
    int lane = threadIdx.x & 31;
    int chain = wg >> 5;        // b*8+h
    int c = wg & 31;
    int b = chain >> 3, h = chain & 7;

    float cum[32], hl[32];
#pragma unroll
    for (int j = 0; j < 32; j++) { cum[j] = (j == lane) ? 1.f : 0.f; hl[j] = 0.f; }

    int t0 = c * CHUNK;
    int bs0 = b * NS + t0;
    int base = (bs0 * NH + h) * 32;
    float kreg  = g_kn[base + lane];
    float qreg  = g_qn[base + lane];
    float kureg = g_kun[base + lane];
    float vs    = g_proj[bs0 * NP1 + 512 + h * 32 + lane];
    float vu    = g_vu[base + lane];
    float4 scv  = *(const float4*)&g_sc[(bs0 * NH + h) * 4];

    for (int t = t0; t < t0 + CHUNK; t++) {
        __syncwarp();
        sk[wq][lane]  = kreg;
        sq[wq][lane]  = qreg;
        sku[wq][lane] = kureg;
        __syncwarp();

        float kN = 0.f, qN = 0.f, kuN = 0.f, vsN = 0.f, vuN = 0.f;
        float4 scN = scv;
        int base2 = base;
        if (t + 1 < t0 + CHUNK) {
            int bs2 = b * NS + t + 1;
            int w2 = bs2 * NH + h;
            base2 = w2 * 32;
            kN  = g_kn[base2 + lane];
            qN  = g_qn[base2 + lane];
            kuN = g_kun[base2 + lane];
            vsN = g_proj[bs2 * NP1 + 512 + h * 32 + lane];
            vuN = g_vu[base2 + lane];
            scN = *(const float4*)&g_sc[w2 * 4];
        }

        float beta = scv.x, Ae = scv.y, Bg = scv.z, kuk = scv.w;
        float ck = 0.f, hk = 0.f;
#pragma unroll
        for (int j4 = 0; j4 < 8; j4++) {
            float4 k4 = *(const float4*)&sk[wq][j4 * 4];
            ck += cum[j4*4+0]*k4.x + cum[j4*4+1]*k4.y + cum[j4*4+2]*k4.z + cum[j4*4+3]*k4.w;
            hk += hl[j4*4+0]*k4.x  + hl[j4*4+1]*k4.y  + hl[j4*4+2]*k4.z  + hl[j4*4+3]*k4.w;
        }
        float e  = Ae * beta * ck;
        float cc = beta * vs - Ae * beta * hk - Bg * beta * kuk * vu;
        float dd = Bg * vu;

        float u = 0.f, wv = 0.f;
#pragma unroll
        for (int j4 = 0; j4 < 8; j4++) {
            float4 k4  = *(const float4*)&sk[wq][j4 * 4];
            float4 ku4 = *(const float4*)&sku[wq][j4 * 4];
            float4 q4  = *(const float4*)&sq[wq][j4 * 4];
            int j = j4 * 4;
            cum[j+0] = Ae * cum[j+0] - e * k4.x;
            cum[j+1] = Ae * cum[j+1] - e * k4.y;
            cum[j+2] = Ae * cum[j+2] - e * k4.z;
            cum[j+3] = Ae * cum[j+3] - e * k4.w;
            hl[j+0] = Ae * hl[j+0] + cc * k4.x + dd * ku4.x;
            hl[j+1] = Ae * hl[j+1] + cc * k4.y + dd * ku4.y;
            hl[j+2] = Ae * hl[j+2] + cc * k4.z + dd * ku4.z;
            hl[j+3] = Ae * hl[j+3] + cc * k4.w + dd * ku4.w;
            u  += cum[j+0]*q4.x + cum[j+1]*q4.y + cum[j+2]*q4.z + cum[j+3]*q4.w;
            wv += hl[j+0]*q4.x  + hl[j+1]*q4.y  + hl[j+2]*q4.z  + hl[j+3]*q4.w;
        }
        g_u[base + lane] = u;
        g_w[base + lane] = wv;

        kreg = kN; qreg = qN; kureg = kuN; vs = vsN; vu = vuN; scv = scN;
        base = base2;
    }
    int mb = (chain * NC + c) * 1024 + lane * 32;
#pragma unroll
    for (int j = 0; j < 32; j += 4) {
        *(float4*)&g_cum[mb + j] = make_float4(cum[j], cum[j+1], cum[j+2], cum[j+3]);
        *(float4*)&g_loc[mb + j] = make_float4(hl[j],  hl[j+1],  hl[j+2],  hl[j+3]);
    }
}

// ---------------- 6. phase 2: fold chunks (smem-staged, prefetched) ---------
__global__ __launch_bounds__(1024) void phase2(const float* __restrict__ carry,
                                               float* __restrict__ outCarry) {
    __shared__ float cumS[2][1024];
    int chain = blockIdx.x;
    int tid = threadIdx.x;
    int j = tid & 31;
    float hreg = carry[chain * 1024 + tid];

    int mb0 = (chain * NC) * 1024;
    float cumNext = g_cum[mb0 + tid];
    float locNext = g_loc[mb0 + tid];

    for (int c = 0; c < NC; c++) {
        int s = c & 1;
        cumS[s][tid] = cumNext;
        float locCur = locNext;
        __syncthreads();
        if (c + 1 < NC) {
            int mb1 = (chain * NC + c + 1) * 1024;
            cumNext = g_cum[mb1 + tid];
            locNext = g_loc[mb1 + tid];
        }
        g_hinit[(chain * NC + c) * 1024 + tid] = hreg;
        float nv = locCur;
#pragma unroll
        for (int m = 0; m < 32; m++)
            nv += __shfl_sync(0xffffffffu, hreg, m) * cumS[s][m * 32 + j];
        hreg = nv;
    }
    outCarry[chain * 1024 + tid] = hreg;  // new_carry
}

// --------- 7. fused phase3 + rms -> fp16: block per (b, chunk) ---------------
__global__ __launch_bounds__(512) void phase3_rms(const float* __restrict__ scale) {
    __shared__ float hin[NH][32 * 33];
    __shared__ float sscale[HID];
    __shared__ float partial[2][2][NH];
    int blk = blockIdx.x;            // b*NC + c
    int b = blk >> 5, c = blk & 31;
    int tid = threadIdx.x;
    int wid = tid >> 5, lane = tid & 31;
    int h = wid & 7, half = wid >> 3;

    for (int idx = tid; idx < NH * 1024; idx += 512) {
        int hh = idx >> 10, e = idx & 1023;
        int i = e >> 5, jj = e & 31;
        hin[hh][i * 33 + jj] = g_hinit[(((b * NH + hh) * NC) + c) * 1024 + e];
    }
    if (tid < HID) sscale[tid] = scale[tid];
    __syncthreads();

    for (int it = 0; it < 32; it++) {
        int t = c * CHUNK + half * 32 + it;
        int bsrow = b * NS + t;
        int base = (bsrow * NH + h) * 32;
        float ul  = g_u[base + lane];
        float acc = g_w[base + lane];
#pragma unroll
        for (int j = 0; j < 32; j++)
            acc += hin[h][lane * 33 + j] * __shfl_sync(0xffffffffu, ul, j);

        float ss = acc * acc;
#pragma unroll
        for (int o = 16; o > 0; o >>= 1) ss += __shfl_xor_sync(0xffffffffu, ss, o);
        int sBuf = it & 1;
        if (lane == 0) partial[half][sBuf][h] = ss;
        __syncthreads();
        float tot = partial[half][sBuf][0] + partial[half][sBuf][1]
                  + partial[half][sBuf][2] + partial[half][sBuf][3]
                  + partial[half][sBuf][4] + partial[half][sBuf][5]
                  + partial[half][sBuf][6] + partial[half][sBuf][7];
        float inv = rsqrtf(tot * (1.f / 256.f) + EPSF);
        float o = acc * inv * sscale[h * 32 + lane];
        g_o2h[bsrow * HID + h * 32 + lane] = __float2half_rn(o);
    }
}

// ---------------- launcher ---------------------------------------------------
extern "C" void kernel_launch(void* const* d_in, const int* in_sizes, int n_in,
                              void* d_out, int out_size) {
    const float* x      = (const float*)d_in[0];
    const float* action = (const float*)d_in[1];
    const float* mask   = (const float*)d_in[2];
    const float* carry  = (const float*)d_in[3];
    const float* Wq     = (const float*)d_in[4];
    const float* Wk     = (const float*)d_in[5];
    const float* Wv     = (const float*)d_in[6];
    const float* Wbeta  = (const float*)d_in[7];
    const float* Walpha = (const float*)d_in[8];
    const float* Wku    = (const float*)d_in[9];
    const float* Wvu    = (const float*)d_in[10];
    const float* Wgamma = (const float*)d_in[11];
    const float* rmssc  = (const float*)d_in[12];
    const float* Wout   = (const float*)d_in[13];
    const float* bout   = (const float*)d_in[14];

    float* outCarry = (float*)d_out;                       // (B,H,D,D) = 32768
    float* y        = (float*)d_out + NB * NH * ND * ND;   // (B,S,F)

    cudaFuncSetAttribute(gemm1_tc, cudaFuncAttributeMaxDynamicSharedMemorySize, SMEM_TOTAL);
    cudaFuncSetAttribute(gemm2_tc, cudaFuncAttributeMaxDynamicSharedMemorySize, SMEM_TOTAL);

    int nprep = N1ELEM + N2ELEM + N3ELEM;
    prep_weights<<<(nprep + 255) / 256, 256>>>(Wq, Wk, Wv, Wbeta, Walpha, Wout);
    xprep_kernel<<<ROWS / 8, 256>>>(x);

    gemm1_tc<<<G1_GRID, 256, SMEM_TOTAL>>>();

    act_kernel<<<(ROWS * NH * 32) / 256, 256>>>(mask, action, Wku, Wvu, Wgamma);

    phase1<<<256, 128>>>();
    phase2<<<32, 1024>>>(carry, outCarry);
    phase3_rms<<<NB * NC, 512>>>(rmssc);

    dim3 g2(NF / 128, ROWS / 128);        // (4, 64)
    gemm2_tc<<<g2, 256, SMEM_TOTAL>>>(bout, y);
}

// round 14
// speedup vs baseline: 1.1122x; 1.0303x over previous
#include <cuda_runtime.h>
#include <cuda_fp16.h>
#include <cstdint>

// Problem constants
#define NB 4
#define NS 2048
#define NF 512
#define NH 8
#define ND 32
#define HID 256
#define ACTF 16
#define ROWS (NB*NS)          // 8192
#define NP1 768               // x-proj output width (q,k,v only)
#define NC 32                 // chunks per sequence
#define CHUNK 64              // NS / NC
#define EPSF 1e-6f

// gemm1 tiling
#define NT1_N 6               // 768/128
#define NT1 (64*NT1_N)        // 384 tiles
#define G1_GRID 296           // 2 CTAs/SM persistent

// ---------------- scratch (static device globals; no allocations) ----------
__device__ __half g_Bt1h[NP1*NF];   // [768,512] W1^T fp16
__device__ __half g_Bt2h[NF*HID];   // [512,256] Wout^T fp16
__device__ __half g_xh[ROWS*NF];    // x as fp16
__device__ __half g_o2h[ROWS*HID];  // rms output fp16 (GEMM2 A)
__device__ float g_WbaT[16*NF];     // transposed beta/alpha weights
__device__ float g_ba[ROWS*16];     // beta/alpha raw projections
__device__ float g_proj[ROWS*NP1];
__device__ float g_u[ROWS*HID];
__device__ float g_w[ROWS*HID];
__device__ float g_cum[32*NC*ND*ND];
__device__ float g_loc[32*NC*ND*ND];
__device__ float g_hinit[32*NC*ND*ND];
__device__ int g_tile_ctr;          // gemm1 persistent tile counter

__device__ __forceinline__ float sigm(float z) { return 1.f / (1.f + __expf(-z)); }

__device__ __forceinline__ uint32_t smem_to_u32(const void* smem_ptr) {
    uint32_t addr;
    asm("{ .reg .u64 tmp; cvta.to.shared.u64 tmp, %1; cvt.u32.u64 %0, tmp; }"
        : "=r"(addr) : "l"(smem_ptr));
    return addr;
}
__device__ __forceinline__ void ldsm_x4(uint32_t* r, uint32_t addr) {
    asm volatile("ldmatrix.sync.aligned.m8n8.x4.shared.b16 {%0,%1,%2,%3}, [%4];"
        : "=r"(r[0]), "=r"(r[1]), "=r"(r[2]), "=r"(r[3]) : "r"(addr));
}
__device__ __forceinline__ void mma16816(float* d, const uint32_t* a, const uint32_t* b) {
    asm volatile(
        "mma.sync.aligned.m16n8k16.row.col.f32.f16.f16.f32 "
        "{%0,%1,%2,%3}, {%4,%5,%6,%7}, {%8,%9}, {%0,%1,%2,%3};"
        : "+f"(d[0]), "+f"(d[1]), "+f"(d[2]), "+f"(d[3])
        : "r"(a[0]), "r"(a[1]), "r"(a[2]), "r"(a[3]), "r"(b[0]), "r"(b[1]));
}
__device__ __forceinline__ void cp16(uint32_t saddr, const void* gaddr) {
    asm volatile("cp.async.cg.shared.global [%0], [%1], 16;" :: "r"(saddr), "l"(gaddr));
}
__device__ __forceinline__ void cp_commit() {
    asm volatile("cp.async.commit_group;" ::: "memory");
}
__device__ __forceinline__ void cp_wait1() {
    asm volatile("cp.async.wait_group 1;" ::: "memory");
}

// ---------------- 1. weight prep (+ tile counter reset) ---------------------
#define N1ELEM (NP1*NF)
#define N2ELEM (NF*HID)
#define N3ELEM (16*NF)
__global__ void prep_weights(const float* __restrict__ Wq, const float* __restrict__ Wk,
                             const float* __restrict__ Wv, const float* __restrict__ Wb,
                             const float* __restrict__ Wa, const float* __restrict__ Wout) {
    int i = blockIdx.x * blockDim.x + threadIdx.x;
    if (i == 0) g_tile_ctr = 0;
    if (i < N1ELEM) {
        int n = i >> 9, k = i & 511;          // Bt1[n,k] = W1[k,n]
        float v;
        if (n < 256)       v = Wq[k*256 + n];
        else if (n < 512)  v = Wk[k*256 + n - 256];
        else               v = Wv[k*256 + n - 512];
        g_Bt1h[i] = __float2half_rn(v);
    } else if (i < N1ELEM + N2ELEM) {
        int j = i - N1ELEM;
        int n = j >> 8, k = j & 255;          // Bt2[n,k] = Wout[k,n]
        g_Bt2h[j] = __float2half_rn(Wout[k*512 + n]);
    } else if (i < N1ELEM + N2ELEM + N3ELEM) {
        int j = i - N1ELEM - N2ELEM;
        int jj = j >> 9, k = j & 511;         // WbaT[jj][k]
        g_WbaT[j] = (jj < 8) ? Wb[k*8 + jj] : Wa[k*8 + (jj - 8)];
    }
}

// ------- 1b. fused: x -> fp16 + beta/alpha projections (one pass over x) ----
__global__ __launch_bounds__(256) void xprep_kernel(const float* __restrict__ x) {
    int w = blockIdx.x * 8 + (threadIdx.x >> 5);     // bs row
    int lane = threadIdx.x & 31;
    const float4* xr = (const float4*)(x + (size_t)w * NF);

    float4 xv[4];
#pragma unroll
    for (int i = 0; i < 4; i++) xv[i] = xr[lane + i * 32];

#pragma unroll
    for (int i = 0; i < 4; i++) {
        __half2 p0 = __floats2half2_rn(xv[i].x, xv[i].y);
        __half2 p1 = __floats2half2_rn(xv[i].z, xv[i].w);
        uint2 hp;
        hp.x = *(uint32_t*)&p0;
        hp.y = *(uint32_t*)&p1;
        *(uint2*)(g_xh + (size_t)w * NF + (lane + i * 32) * 4) = hp;
    }

#pragma unroll
    for (int j = 0; j < 16; j++) {
        const float4* wt = (const float4*)(g_WbaT + j * NF);
        float s = 0.f;
#pragma unroll
        for (int i = 0; i < 4; i++) {
            float4 wv = wt[lane + i * 32];
            s += xv[i].x*wv.x + xv[i].y*wv.y + xv[i].z*wv.z + xv[i].w*wv.w;
        }
#pragma unroll
        for (int o = 16; o > 0; o >>= 1) s += __shfl_xor_sync(0xffffffffu, s, o);
        if (lane == 0) g_ba[w * 16 + j] = s;
    }
}

// ---------------- 2. HMMA fp16 GEMM (single product), 3-stage cp.async ------
#define ROWB 80                 // padded smem row stride (bytes)
#define OAH 0
#define OBH 10240
#define STG 20480
#define STAGES 3
#define SMEM_TOTAL (STAGES*STG)

__device__ __forceinline__ void gemm_tile(const __half* __restrict__ Ah,
                                          const __half* __restrict__ Bh,
                                          float* __restrict__ C,
                                          const float* __restrict__ bias,
                                          int N, int K, int m0, int n0,
                                          char* smem, uint32_t sb) {
    int tid = threadIdx.x, lane = tid & 31, wid = tid >> 5;
    int wm = (wid >> 2) * 64, wn = (wid & 3) * 32;

    uint32_t aOff = (uint32_t)((wm + (lane & 7) + ((lane >> 3) & 1) * 8) * ROWB
                               + ((lane >> 4) * 8) * 2);
    uint32_t bOff = (uint32_t)((wn + (lane & 7) + ((lane >> 4) & 1) * 8) * ROWB
                               + (((lane >> 3) & 1) * 8) * 2);

    float acc[4][4][4];
#pragma unroll
    for (int mt = 0; mt < 4; mt++)
#pragma unroll
        for (int nt = 0; nt < 4; nt++)
#pragma unroll
            for (int e = 0; e < 4; e++) acc[mt][nt][e] = 0.f;

    int crow = tid >> 1;
    int cel = (tid & 1) * 16;
    uint32_t sOff = (uint32_t)(crow * ROWB + (tid & 1) * 32);
    const __half* pAh = Ah + (size_t)(m0 + crow) * K + cel;
    const __half* pBh = Bh + (size_t)(n0 + crow) * K + cel;
    int nkc = K >> 5;

#define CP_STAGE(kc, s) do {                                            \
        uint32_t _stb = sb + (s) * STG;                                 \
        int _ko = (kc) * 32;                                            \
        cp16(_stb + OAH + sOff,      pAh + _ko);                        \
        cp16(_stb + OAH + sOff + 16, pAh + _ko + 8);                    \
        cp16(_stb + OBH + sOff,      pBh + _ko);                        \
        cp16(_stb + OBH + sOff + 16, pBh + _ko + 8);                    \
    } while(0)

    CP_STAGE(0, 0); cp_commit();
    CP_STAGE(1, 1); cp_commit();

    int s = 0;
    for (int kc = 0; kc < nkc; kc++) {
        cp_wait1();
        __syncthreads();

        int kn = kc + 2;
        if (kn < nkc) CP_STAGE(kn, (s + 2 >= STAGES) ? s + 2 - STAGES : s + 2);
        cp_commit();

        uint32_t stb = sb + s * STG;
#pragma unroll
        for (int ks = 0; ks < 2; ks++) {
            uint32_t kb = ks * 32;
            uint32_t af[4][4], bhF[2][4];
#pragma unroll
            for (int mt = 0; mt < 4; mt++)
                ldsm_x4(af[mt], stb + OAH + aOff + mt * (16 * ROWB) + kb);
#pragma unroll
            for (int np = 0; np < 2; np++)
                ldsm_x4(bhF[np], stb + OBH + bOff + np * (16 * ROWB) + kb);
#pragma unroll
            for (int mt = 0; mt < 4; mt++)
#pragma unroll
                for (int nt = 0; nt < 4; nt++)
                    mma16816(acc[mt][nt], af[mt], &bhF[nt >> 1][(nt & 1) * 2]);
        }
        s = (s + 1 >= STAGES) ? 0 : s + 1;
    }
#undef CP_STAGE

#pragma unroll
    for (int mt = 0; mt < 4; mt++) {
        int r0 = m0 + wm + mt * 16 + (lane >> 2);
#pragma unroll
        for (int nt = 0; nt < 4; nt++) {
            int col = n0 + wn + nt * 8 + (lane & 3) * 2;
            float b0 = 0.f, b1 = 0.f;
            if (bias) { b0 = bias[col]; b1 = bias[col + 1]; }
            float2 v0, v1;
            v0.x = acc[mt][nt][0] + b0; v0.y = acc[mt][nt][1] + b1;
            v1.x = acc[mt][nt][2] + b0; v1.y = acc[mt][nt][3] + b1;
            *(float2*)(C + (size_t)r0 * N + col) = v0;
            *(float2*)(C + (size_t)(r0 + 8) * N + col) = v1;
        }
    }
}

// gemm1: persistent CTAs, dynamic tile scheduler
__global__ __launch_bounds__(256, 2) void gemm1_tc() {
    extern __shared__ char smem[];
    __shared__ int s_tile;
    uint32_t sb = smem_to_u32(smem);
    for (;;) {
        if (threadIdx.x == 0) s_tile = atomicAdd(&g_tile_ctr, 1);
        __syncthreads();
        int tile = s_tile;
        if (tile >= NT1) return;
        int m0 = (tile / NT1_N) * 128;
        int n0 = (tile % NT1_N) * 128;
        gemm_tile(g_xh, g_Bt1h, g_proj, nullptr, NP1, NF, m0, n0, smem, sb);
    }
}
// gemm2: static grid (256 CTAs = single wave)
__global__ __launch_bounds__(256, 2) void gemm2_tc(const float* __restrict__ bout,
                                                   float* __restrict__ y) {
    extern __shared__ char smem[];
    uint32_t sb = smem_to_u32(smem);
    gemm_tile(g_o2h, g_Bt2h, y, bout, NF, HID,
              blockIdx.y * 128, blockIdx.x * 128, smem, sb);
}

// ---------------- 5. FUSED act + phase1 chunked scan -------------------------
__global__ __launch_bounds__(128) void phase1(const float* __restrict__ mask,
                                              const float* __restrict__ action,
                                              const float* __restrict__ Wku,
                                              const float* __restrict__ Wvu,
                                              const float* __restrict__ Wg) {
    __shared__ float s_k[4][32], s_q[4][32], s_ku[4][32];
    int wq = threadIdx.x >> 5;
    int wg = blockIdx.x * 4 + wq;                   // 0..1023
    int lane = threadIdx.x & 31;
    int chain = wg >> 5;        // b*8+h
    int c = wg & 31;
    int b = chain >> 3, h = chain & 7;
    int col = h * 32 + lane;

    // hoist action weights for this (h, lane) into registers
    float wku[ACTF], wvu[ACTF], wgv[ACTF];
#pragma unroll
    for (int i = 0; i < ACTF; i++) {
        wku[i] = Wku[i * HID + col];
        wvu[i] = Wvu[i * HID + col];
        wgv[i] = Wg[i * NH + h];
    }

    float cum[32], hl[32];
#pragma unroll
    for (int j = 0; j < 32; j++) { cum[j] = (j == lane) ? 1.f : 0.f; hl[j] = 0.f; }

    int t0 = c * CHUNK;

    // raw prefetch registers for current timestep
    int bs = b * NS + t0;
    float qr = g_proj[bs * NP1 + col];
    float kr = g_proj[bs * NP1 + 256 + col];
    float vs = g_proj[bs * NP1 + 512 + col];
    const float4* ap = (const float4*)(action + bs * ACTF);
    float4 a0 = ap[0], a1 = ap[1], a2 = ap[2], a3 = ap[3];
    float br = g_ba[bs * 16 + h];
    float alr = g_ba[bs * 16 + 8 + h];
    float mm = mask[bs];

    for (int t = t0; t < t0 + CHUNK; t++) {
        int base = ((b * NS + t) * NH + h) * 32;

        // ---- prefetch raw t+1 (independent of everything below) ----
        float qrN = 0.f, krN = 0.f, vsN = 0.f, brN = 0.f, alrN = 0.f, mmN = 0.f;
        float4 a0N = a0, a1N = a1, a2N = a2, a3N = a3;
        if (t + 1 < t0 + CHUNK) {
            int bs2 = b * NS + t + 1;
            qrN = g_proj[bs2 * NP1 + col];
            krN = g_proj[bs2 * NP1 + 256 + col];
            vsN = g_proj[bs2 * NP1 + 512 + col];
            const float4* ap2 = (const float4*)(action + bs2 * ACTF);
            a0N = ap2[0]; a1N = ap2[1]; a2N = ap2[2]; a3N = ap2[3];
            brN = g_ba[bs2 * 16 + h];
            alrN = g_ba[bs2 * 16 + 8 + h];
            mmN = mask[bs2];
        }

        // ---- act: action projection (registers) ----
        float a[ACTF] = { a0.x,a0.y,a0.z,a0.w, a1.x,a1.y,a1.z,a1.w,
                          a2.x,a2.y,a2.z,a2.w, a3.x,a3.y,a3.z,a3.w };
        float kur = 0.f, vur = 0.f, gr = 0.f;
#pragma unroll
        for (int i = 0; i < ACTF; i++) {
            kur += a[i] * wku[i];
            vur += a[i] * wvu[i];
            gr  += a[i] * wgv[i];
        }

        // ---- act: silu + l2norm ----
        float q  = qr * sigm(qr);
        float k  = kr * sigm(kr);
        float ku = kur * sigm(kur);
        float nq = q*q, nk = k*k, nku = ku*ku;
#pragma unroll
        for (int o = 16; o > 0; o >>= 1) {
            nq  += __shfl_xor_sync(0xffffffffu, nq,  o);
            nk  += __shfl_xor_sync(0xffffffffu, nk,  o);
            nku += __shfl_xor_sync(0xffffffffu, nku, o);
        }
        q  *= rsqrtf(nq  + EPSF);
        k  *= rsqrtf(nk  + EPSF);
        ku *= rsqrtf(nku + EPSF);
        float dk = ku * k;
#pragma unroll
        for (int o = 16; o > 0; o >>= 1) dk += __shfl_xor_sync(0xffffffffu, dk, o);

        float beta = sigm(br);
        float Ae   = sigm(alr) * (1.f - mm);
        float Bg   = sigm(gr);
        float vu   = vur;
        float kuk  = dk;

        // ---- broadcast k/q/ku through smem ----
        __syncwarp();
        s_k[wq][lane]  = k;
        s_q[wq][lane]  = q;
        s_ku[wq][lane] = ku;
        __syncwarp();

        // ---- scan update ----
        float ck = 0.f, hk = 0.f;
#pragma unroll
        for (int j4 = 0; j4 < 8; j4++) {
            float4 k4 = *(const float4*)&s_k[wq][j4 * 4];
            ck += cum[j4*4+0]*k4.x + cum[j4*4+1]*k4.y + cum[j4*4+2]*k4.z + cum[j4*4+3]*k4.w;
            hk += hl[j4*4+0]*k4.x  + hl[j4*4+1]*k4.y  + hl[j4*4+2]*k4.z  + hl[j4*4+3]*k4.w;
        }
        float e  = Ae * beta * ck;
        float cc = beta * vs - Ae * beta * hk - Bg * beta * kuk * vu;
        float dd = Bg * vu;

        float u = 0.f, wv = 0.f;
#pragma unroll
        for (int j4 = 0; j4 < 8; j4++) {
            float4 k4  = *(const float4*)&s_k[wq][j4 * 4];
            float4 ku4 = *(const float4*)&s_ku[wq][j4 * 4];
            float4 q4  = *(const float4*)&s_q[wq][j4 * 4];
            int j = j4 * 4;
            cum[j+0] = Ae * cum[j+0] - e * k4.x;
            cum[j+1] = Ae * cum[j+1] - e * k4.y;
            cum[j+2] = Ae * cum[j+2] - e * k4.z;
            cum[j+3] = Ae * cum[j+3] - e * k4.w;
            hl[j+0] = Ae * hl[j+0] + cc * k4.x + dd * ku4.x;
            hl[j+1] = Ae * hl[j+1] + cc * k4.y + dd * ku4.y;
            hl[j+2] = Ae * hl[j+2] + cc * k4.z + dd * ku4.z;
            hl[j+3] = Ae * hl[j+3] + cc * k4.w + dd * ku4.w;
            u  += cum[j+0]*q4.x + cum[j+1]*q4.y + cum[j+2]*q4.z + cum[j+3]*q4.w;
            wv += hl[j+0]*q4.x  + hl[j+1]*q4.y  + hl[j+2]*q4.z  + hl[j+3]*q4.w;
        }
        g_u[base + lane] = u;
        g_w[base + lane] = wv;

        // rotate prefetched raw
        qr = qrN; kr = krN; vs = vsN;
        a0 = a0N; a1 = a1N; a2 = a2N; a3 = a3N;
        br = brN; alr = alrN; mm = mmN;
    }
    int mb = (chain * NC + c) * 1024 + lane * 32;
#pragma unroll
    for (int j = 0; j < 32; j += 4) {
        *(float4*)&g_cum[mb + j] = make_float4(cum[j], cum[j+1], cum[j+2], cum[j+3]);
        *(float4*)&g_loc[mb + j] = make_float4(hl[j],  hl[j+1],  hl[j+2],  hl[j+3]);
    }
}

// ---------------- 6. phase 2: fold chunks (smem-staged, prefetched) ---------
__global__ __launch_bounds__(1024) void phase2(const float* __restrict__ carry,
                                               float* __restrict__ outCarry) {
    __shared__ float cumS[2][1024];
    int chain = blockIdx.x;
    int tid = threadIdx.x;
    int j = tid & 31;
    float hreg = carry[chain * 1024 + tid];

    int mb0 = (chain * NC) * 1024;
    float cumNext = g_cum[mb0 + tid];
    float locNext = g_loc[mb0 + tid];

    for (int c = 0; c < NC; c++) {
        int s = c & 1;
        cumS[s][tid] = cumNext;
        float locCur = locNext;
        __syncthreads();
        if (c + 1 < NC) {
            int mb1 = (chain * NC + c + 1) * 1024;
            cumNext = g_cum[mb1 + tid];
            locNext = g_loc[mb1 + tid];
        }
        g_hinit[(chain * NC + c) * 1024 + tid] = hreg;
        float nv = locCur;
#pragma unroll
        for (int m = 0; m < 32; m++)
            nv += __shfl_sync(0xffffffffu, hreg, m) * cumS[s][m * 32 + j];
        hreg = nv;
    }
    outCarry[chain * 1024 + tid] = hreg;  // new_carry
}

// --------- 7. fused phase3 + rms -> fp16: block per (b, chunk) ---------------
__global__ __launch_bounds__(512) void phase3_rms(const float* __restrict__ scale) {
    __shared__ float hin[NH][32 * 33];
    __shared__ float sscale[HID];
    __shared__ float partial[2][2][NH];
    int blk = blockIdx.x;            // b*NC + c
    int b = blk >> 5, c = blk & 31;
    int tid = threadIdx.x;
    int wid = tid >> 5, lane = tid & 31;
    int h = wid & 7, half = wid >> 3;

    for (int idx = tid; idx < NH * 1024; idx += 512) {
        int hh = idx >> 10, e = idx & 1023;
        int i = e >> 5, jj = e & 31;
        hin[hh][i * 33 + jj] = g_hinit[(((b * NH + hh) * NC) + c) * 1024 + e];
    }
    if (tid < HID) sscale[tid] = scale[tid];
    __syncthreads();

    for (int it = 0; it < 32; it++) {
        int t = c * CHUNK + half * 32 + it;
        int bsrow = b * NS + t;
        int base = (bsrow * NH + h) * 32;
        float ul  = g_u[base + lane];
        float acc = g_w[base + lane];
#pragma unroll
        for (int j = 0; j < 32; j++)
            acc += hin[h][lane * 33 + j] * __shfl_sync(0xffffffffu, ul, j);

        float ss = acc * acc;
#pragma unroll
        for (int o = 16; o > 0; o >>= 1) ss += __shfl_xor_sync(0xffffffffu, ss, o);
        int sBuf = it & 1;
        if (lane == 0) partial[half][sBuf][h] = ss;
        __syncthreads();
        float tot = partial[half][sBuf][0] + partial[half][sBuf][1]
                  + partial[half][sBuf][2] + partial[half][sBuf][3]
                  + partial[half][sBuf][4] + partial[half][sBuf][5]
                  + partial[half][sBuf][6] + partial[half][sBuf][7];
        float inv = rsqrtf(tot * (1.f / 256.f) + EPSF);
        float o = acc * inv * sscale[h * 32 + lane];
        g_o2h[bsrow * HID + h * 32 + lane] = __float2half_rn(o);
    }
}

// ---------------- launcher ---------------------------------------------------
extern "C" void kernel_launch(void* const* d_in, const int* in_sizes, int n_in,
                              void* d_out, int out_size) {
    const float* x      = (const float*)d_in[0];
    const float* action = (const float*)d_in[1];
    const float* mask   = (const float*)d_in[2];
    const float* carry  = (const float*)d_in[3];
    const float* Wq     = (const float*)d_in[4];
    const float* Wk     = (const float*)d_in[5];
    const float* Wv     = (const float*)d_in[6];
    const float* Wbeta  = (const float*)d_in[7];
    const float* Walpha = (const float*)d_in[8];
    const float* Wku    = (const float*)d_in[9];
    const float* Wvu    = (const float*)d_in[10];
    const float* Wgamma = (const float*)d_in[11];
    const float* rmssc  = (const float*)d_in[12];
    const float* Wout   = (const float*)d_in[13];
    const float* bout   = (const float*)d_in[14];

    float* outCarry = (float*)d_out;                       // (B,H,D,D) = 32768
    float* y        = (float*)d_out + NB * NH * ND * ND;   // (B,S,F)

    cudaFuncSetAttribute(gemm1_tc, cudaFuncAttributeMaxDynamicSharedMemorySize, SMEM_TOTAL);
    cudaFuncSetAttribute(gemm2_tc, cudaFuncAttributeMaxDynamicSharedMemorySize, SMEM_TOTAL);

    int nprep = N1ELEM + N2ELEM + N3ELEM;
    prep_weights<<<(nprep + 255) / 256, 256>>>(Wq, Wk, Wv, Wbeta, Walpha, Wout);
    xprep_kernel<<<ROWS / 8, 256>>>(x);

    gemm1_tc<<<G1_GRID, 256, SMEM_TOTAL>>>();

    phase1<<<256, 128>>>(mask, action, Wku, Wvu, Wgamma);
    phase2<<<32, 1024>>>(carry, outCarry);
    phase3_rms<<<NB * NC, 512>>>(rmssc);

    dim3 g2(NF / 128, ROWS / 128);        // (4, 64)
    gemm2_tc<<<g2, 256, SMEM_TOTAL>>>(bout, y);
}